// round 7
// baseline (speedup 1.0000x reference)
#include <cuda_runtime.h>
#include <cuda_bf16.h>
#include <math.h>

#define N_ROWS 32768
#define DIM    512
#define NQ     8
#define NK     4096
#define THRESH 3e-4f

// ---- dynamic smem layout for the fast kernel (u32 units) ----
#define SA_STRIDE 260                      // 256 u32 payload + pad4 -> banks (4r+c)%32
#define SB_STRIDE 36                       // 32 u32 payload + pad4
#define A_OFF_HI  0
#define A_OFF_LO  (64 * SA_STRIDE)         // 16640
#define B_OFF_HI  (2 * 64 * SA_STRIDE)     // 33280
#define B_OFF_LO  (B_OFF_HI + 128 * SB_STRIDE)
#define RED_OFF   (B_OFF_HI + 2 * 128 * SB_STRIDE)
#define SMEM_U32  (RED_OFF + 3 * 256)
#define SMEM_BYTES (SMEM_U32 * 4)          // 173056

// Scratch (allocation-free rule: __device__ globals, referenced by name only)
__device__ float g_res[(size_t)N_ROWS * DIM];
__device__ float g_anorm[(size_t)N_ROWS * DIM];
__device__ float g_bnorm[(size_t)NK * DIM];
__device__ float g_rnorm[N_ROWS];
__device__ float g_cnorm[NK];
__device__ int   g_ids[N_ROWS];
__device__ int   g_flag_count;
__device__ int   g_flag_rows[N_ROWS];
__device__ uint4 g_ahi[(size_t)N_ROWS * DIM / 8];
__device__ uint4 g_alo[(size_t)N_ROWS * DIM / 8];
__device__ uint4 g_bhi[(size_t)NK * DIM / 8];
__device__ uint4 g_blo[(size_t)NK * DIM / 8];

// ---------------------------------------------------------------------------
// helpers
// ---------------------------------------------------------------------------
__device__ __forceinline__ unsigned long long packf2(float lo, float hi) {
    unsigned long long r;
    asm("mov.b64 %0, {%1, %2};" : "=l"(r) : "f"(lo), "f"(hi));
    return r;
}
__device__ __forceinline__ void fmaf2(unsigned long long& d,
                                      unsigned long long a, unsigned long long b) {
    asm("fma.rn.f32x2 %0, %1, %2, %0;" : "+l"(d) : "l"(a), "l"(b));
}
__device__ __forceinline__ void unpackf2(unsigned long long p, float& lo, float& hi) {
    asm("mov.b64 {%0, %1}, %2;" : "=f"(lo), "=f"(hi) : "l"(p));
}
__device__ __forceinline__ unsigned bf2u(float x, float y) {   // x -> low 16 bits
    __nv_bfloat162 v = __floats2bfloat162_rn(x, y);
    return *(unsigned*)&v;
}
__device__ __forceinline__ void mma_bf16(float& c0, float& c1, float& c2, float& c3,
                                         unsigned a0, unsigned a1, unsigned a2, unsigned a3,
                                         unsigned b0, unsigned b1) {
    asm volatile(
        "mma.sync.aligned.m16n8k16.row.col.f32.bf16.bf16.f32 "
        "{%0,%1,%2,%3}, {%4,%5,%6,%7}, {%8,%9}, {%0,%1,%2,%3};"
        : "+f"(c0), "+f"(c1), "+f"(c2), "+f"(c3)
        : "r"(a0), "r"(a1), "r"(a2), "r"(a3), "r"(b0), "r"(b1));
}

// ---------------------------------------------------------------------------
// init: res = x, hard(out) = 0, flag counter = 0
// ---------------------------------------------------------------------------
__global__ __launch_bounds__(256) void init_kernel(const float* __restrict__ x,
                                                   float* __restrict__ hard) {
    if (blockIdx.x == 0 && threadIdx.x == 0) g_flag_count = 0;
    size_t i = ((size_t)blockIdx.x * 256 + threadIdx.x) * 4;
    float4 v = *(const float4*)(x + i);
    *(float4*)(g_res + i) = v;
    *(float4*)(hard + i) = make_float4(0.f, 0.f, 0.f, 0.f);
}

// ---------------------------------------------------------------------------
// Row L2 norm, STRICT SEQUENTIAL fp32 — proven bit-exact vs reference.
// ---------------------------------------------------------------------------
__device__ __forceinline__ float seq_row_norm(const float* __restrict__ s) {
    float acc = 0.f;
    #pragma unroll 8
    for (int i = 0; i < DIM; i += 4) {
        float4 v = *(const float4*)(s + i);
        acc = __fadd_rn(acc, __fmul_rn(v.x, v.x));
        acc = __fadd_rn(acc, __fmul_rn(v.y, v.y));
        acc = __fadd_rn(acc, __fmul_rn(v.z, v.z));
        acc = __fadd_rn(acc, __fmul_rn(v.w, v.w));
    }
    return fmaxf(__fsqrt_rn(acc), 1e-12f);
}
__global__ __launch_bounds__(256) void res_norm_kernel() {
    int r = blockIdx.x * 256 + threadIdx.x;
    g_rnorm[r] = seq_row_norm(g_res + (size_t)r * DIM);
}
__global__ __launch_bounds__(256) void cb_norm_kernel(const float* __restrict__ cbq) {
    int r = blockIdx.x * 256 + threadIdx.x;
    g_cnorm[r] = seq_row_norm(cbq + (size_t)r * DIM);
}

// ---------------------------------------------------------------------------
// divide (IEEE rn) + bf16 hi/lo split. One thread handles 8 elements.
// ---------------------------------------------------------------------------
__device__ __forceinline__ void div_split8(const float* __restrict__ src, float n,
                                           float* __restrict__ anorm,
                                           uint4* __restrict__ hi4,
                                           uint4* __restrict__ lo4) {
    float an[8];
    float4 v0 = *(const float4*)(src);
    float4 v1 = *(const float4*)(src + 4);
    an[0] = __fdiv_rn(v0.x, n); an[1] = __fdiv_rn(v0.y, n);
    an[2] = __fdiv_rn(v0.z, n); an[3] = __fdiv_rn(v0.w, n);
    an[4] = __fdiv_rn(v1.x, n); an[5] = __fdiv_rn(v1.y, n);
    an[6] = __fdiv_rn(v1.z, n); an[7] = __fdiv_rn(v1.w, n);
    *(float4*)(anorm)     = make_float4(an[0], an[1], an[2], an[3]);
    *(float4*)(anorm + 4) = make_float4(an[4], an[5], an[6], an[7]);
    float lo[8];
    #pragma unroll
    for (int j = 0; j < 8; j++) {
        __nv_bfloat16 h = __float2bfloat16_rn(an[j]);
        lo[j] = __fsub_rn(an[j], __bfloat162float(h));
    }
    uint4 uh, ul;
    uh.x = bf2u(an[0], an[1]); uh.y = bf2u(an[2], an[3]);
    uh.z = bf2u(an[4], an[5]); uh.w = bf2u(an[6], an[7]);
    ul.x = bf2u(lo[0], lo[1]); ul.y = bf2u(lo[2], lo[3]);
    ul.z = bf2u(lo[4], lo[5]); ul.w = bf2u(lo[6], lo[7]);
    *hi4 = uh; *lo4 = ul;
}

__global__ __launch_bounds__(256) void res_div_split_kernel() {
    size_t g = (size_t)blockIdx.x * 256 + threadIdx.x;   // one group of 8 elems
    size_t i = g * 8;
    float n = g_rnorm[i >> 9];
    div_split8(g_res + i, n, g_anorm + i, &g_ahi[g], &g_alo[g]);
}
__global__ __launch_bounds__(256) void cb_div_split_kernel(const float* __restrict__ cbq) {
    size_t g = (size_t)blockIdx.x * 256 + threadIdx.x;
    size_t i = g * 8;
    float n = g_cnorm[i >> 9];
    div_split8(cbq + i, n, g_bnorm + i, &g_bhi[g], &g_blo[g]);
}

// ---------------------------------------------------------------------------
// FAST PASS: bf16-split mma.sync GEMM + top-2 argmax + flagging.
// Block = 64 rows, 8 warps (2m x 4n), ct-tiles of 128 cols, k staged by 64.
// acc = a_hi*b_hi + a_hi*b_lo + a_lo*b_hi (fp32 accum). Strict error vs the
// exact fp32 chain < 8e-5; rows with top-2 gap < THRESH get exact rescore.
// ---------------------------------------------------------------------------
__global__ __launch_bounds__(256, 1) void fast_gemm_kernel() {
    extern __shared__ unsigned s[];
    const int tid  = threadIdx.x;
    const int lane = tid & 31;
    const int wid  = tid >> 5;
    const int wm   = wid >> 2;          // 0..1
    const int wn   = wid & 3;           // 0..3
    const int g4   = lane >> 2;         // groupID
    const int tig  = lane & 3;          // thread-in-group
    const int row0 = blockIdx.x * 64;

    // A (hi, lo) -> smem, full K, once per block
    #pragma unroll
    for (int m = 0; m < 2; m++) {
        const uint4* src = m ? g_alo : g_ahi;
        const unsigned off = m ? A_OFF_LO : A_OFF_HI;
        #pragma unroll
        for (int it = 0; it < 16; it++) {
            int idx = tid + it * 256;            // 0..4095
            int r = idx >> 6, qd = idx & 63;
            uint4 v = src[(size_t)(row0 + r) * 64 + qd];
            *(uint4*)&s[off + r * SA_STRIDE + qd * 4] = v;
        }
    }

    float best[4], sec[4];
    int   bidx[4];
    #pragma unroll
    for (int i = 0; i < 4; i++) { best[i] = -3.4e38f; sec[i] = -3.4e38f; bidx[i] = 0; }

    for (int ct = 0; ct < NK / 128; ct++) {
        float acc[2][4][4];
        #pragma unroll
        for (int mt = 0; mt < 2; mt++)
            #pragma unroll
            for (int nt = 0; nt < 4; nt++)
                #pragma unroll
                for (int c = 0; c < 4; c++) acc[mt][nt][c] = 0.f;

        for (int kc = 0; kc < 8; kc++) {        // 64-k chunks
            __syncthreads();
            #pragma unroll
            for (int m = 0; m < 2; m++) {
                const uint4* src = m ? g_blo : g_bhi;
                const unsigned off = m ? B_OFF_LO : B_OFF_HI;
                #pragma unroll
                for (int it = 0; it < 4; it++) {
                    int idx = tid + it * 256;    // 0..1023
                    int c = idx >> 3, u4 = idx & 7;
                    uint4 v = src[(size_t)(ct * 128 + c) * 64 + kc * 8 + u4];
                    *(uint4*)&s[off + c * SB_STRIDE + u4 * 4] = v;
                }
            }
            __syncthreads();

            #pragma unroll
            for (int ks = 0; ks < 4; ks++) {
                const int kg = kc * 4 + ks;
                unsigned ah[2][4], al[2][4];
                #pragma unroll
                for (int mt = 0; mt < 2; mt++) {
                    unsigned base = (wm * 32 + mt * 16 + g4) * SA_STRIDE + kg * 8 + tig;
                    ah[mt][0] = s[A_OFF_HI + base];
                    ah[mt][1] = s[A_OFF_HI + base + 8 * SA_STRIDE];
                    ah[mt][2] = s[A_OFF_HI + base + 4];
                    ah[mt][3] = s[A_OFF_HI + base + 8 * SA_STRIDE + 4];
                    al[mt][0] = s[A_OFF_LO + base];
                    al[mt][1] = s[A_OFF_LO + base + 8 * SA_STRIDE];
                    al[mt][2] = s[A_OFF_LO + base + 4];
                    al[mt][3] = s[A_OFF_LO + base + 8 * SA_STRIDE + 4];
                }
                #pragma unroll
                for (int nt = 0; nt < 4; nt++) {
                    unsigned bb = (wn * 32 + nt * 8 + g4) * SB_STRIDE + ks * 8 + tig;
                    unsigned bh0 = s[B_OFF_HI + bb], bh1 = s[B_OFF_HI + bb + 4];
                    unsigned bl0 = s[B_OFF_LO + bb], bl1 = s[B_OFF_LO + bb + 4];
                    #pragma unroll
                    for (int mt = 0; mt < 2; mt++) {
                        float* c = acc[mt][nt];
                        mma_bf16(c[0], c[1], c[2], c[3],
                                 ah[mt][0], ah[mt][1], ah[mt][2], ah[mt][3], bh0, bh1);
                        mma_bf16(c[0], c[1], c[2], c[3],
                                 ah[mt][0], ah[mt][1], ah[mt][2], ah[mt][3], bl0, bl1);
                        mma_bf16(c[0], c[1], c[2], c[3],
                                 al[mt][0], al[mt][1], al[mt][2], al[mt][3], bh0, bh1);
                    }
                }
            }
        }

        // epilogue: per-thread top-2, columns strictly ascending
        #pragma unroll
        for (int nt = 0; nt < 4; nt++) {
            int colbase = ct * 128 + wn * 32 + nt * 8 + tig * 2;
            #pragma unroll
            for (int mt = 0; mt < 2; mt++) {
                #pragma unroll
                for (int h = 0; h < 2; h++) {
                    int slot = mt * 2 + h;
                    float v0 = acc[mt][nt][h * 2 + 0];
                    float v1 = acc[mt][nt][h * 2 + 1];
                    if (v0 > best[slot]) { sec[slot] = best[slot]; best[slot] = v0; bidx[slot] = colbase; }
                    else if (v0 > sec[slot]) sec[slot] = v0;
                    if (v1 > best[slot]) { sec[slot] = best[slot]; best[slot] = v1; bidx[slot] = colbase + 1; }
                    else if (v1 > sec[slot]) sec[slot] = v1;
                }
            }
        }
    }

    // intra-warp top-2 merge across the 4 lanes sharing each row
    #pragma unroll
    for (int off = 1; off <= 2; off <<= 1) {
        #pragma unroll
        for (int sl = 0; sl < 4; sl++) {
            float ob = __shfl_xor_sync(0xffffffffu, best[sl], off);
            float os = __shfl_xor_sync(0xffffffffu, sec[sl], off);
            int   oi = __shfl_xor_sync(0xffffffffu, bidx[sl], off);
            if (ob > best[sl] || (ob == best[sl] && oi < bidx[sl])) {
                sec[sl] = fmaxf(best[sl], os);
                best[sl] = ob; bidx[sl] = oi;
            } else {
                sec[sl] = fmaxf(sec[sl], ob);
            }
        }
    }

    // cross-warp (wn) merge via smem
    float* rb = (float*)&s[RED_OFF];
    float* rs = rb + 256;
    int*   ri = (int*)(rs + 256);
    __syncthreads();                           // everyone past compute/smem use
    if (tig == 0) {
        #pragma unroll
        for (int sl = 0; sl < 4; sl++) {
            int rloc = wm * 32 + (sl >> 1) * 16 + (sl & 1) * 8 + g4;
            rb[wn * 64 + rloc] = best[sl];
            rs[wn * 64 + rloc] = sec[sl];
            ri[wn * 64 + rloc] = bidx[sl];
        }
    }
    __syncthreads();
    if (tid < 64) {
        float b = -3.4e38f, s2 = -3.4e38f; int bi = 0;
        #pragma unroll
        for (int w = 0; w < 4; w++) {
            float wb = rb[w * 64 + tid], ws = rs[w * 64 + tid];
            int   wi = ri[w * 64 + tid];
            if (wb > b || (wb == b && wi < bi)) {
                s2 = fmaxf(b, ws); b = wb; bi = wi;
            } else {
                s2 = fmaxf(s2, wb);
            }
        }
        int row = row0 + tid;
        g_ids[row] = bi;
        if (b - s2 < THRESH) {
            int slot = atomicAdd(&g_flag_count, 1);
            g_flag_rows[slot] = row;
        }
    }
}

// ---------------------------------------------------------------------------
// EXACT RESCORE: bit-exact FFMA2 GEMM + argmax over flagged rows only.
// Same math as the proven round-6 kernel, rows gathered via g_flag_rows.
// ---------------------------------------------------------------------------
__global__ __launch_bounds__(256) void rescore_kernel() {
    const int count = g_flag_count;
    const int base  = blockIdx.x * 128;
    if (base >= count) return;

    __shared__ float As[32][130];
    __shared__ float Bs[32][130];

    const int tid = threadIdx.x;
    const int tx  = tid & 15;
    const int ty  = tid >> 4;

    float best[8];
    int   bidx[8];
    #pragma unroll
    for (int r = 0; r < 8; r++) { best[r] = -3.4e38f; bidx[r] = 0; }

    for (int ct = 0; ct < NK; ct += 128) {
        unsigned long long accp[8][4];
        #pragma unroll
        for (int r = 0; r < 8; r++)
            #pragma unroll
            for (int j = 0; j < 4; j++) accp[r][j] = 0ull;

        for (int kk = 0; kk < DIM; kk += 32) {
            __syncthreads();
            #pragma unroll
            for (int t = 0; t < 4; t++) {
                int f = tid + t * 256;
                int r = f >> 3;
                int c = (f & 7) << 2;
                int slot = base + r;
                int grow = (slot < count) ? g_flag_rows[slot] : g_flag_rows[0];
                float4 va = *(const float4*)(g_anorm + (size_t)grow * DIM + kk + c);
                As[c + 0][r] = va.x; As[c + 1][r] = va.y;
                As[c + 2][r] = va.z; As[c + 3][r] = va.w;
                float4 vb = *(const float4*)(g_bnorm + (size_t)(ct + r) * DIM + kk + c);
                Bs[c + 0][r] = vb.x; Bs[c + 1][r] = vb.y;
                Bs[c + 2][r] = vb.z; Bs[c + 3][r] = vb.w;
            }
            __syncthreads();

            #pragma unroll
            for (int k = 0; k < 32; k++) {
                unsigned long long bp[4];
                #pragma unroll
                for (int j = 0; j < 4; j++) {
                    float2 b2 = *(const float2*)&Bs[k][2 * tx + 32 * j];
                    bp[j] = packf2(b2.x, b2.y);
                }
                #pragma unroll
                for (int i = 0; i < 4; i++) {
                    float2 a2 = *(const float2*)&As[k][2 * ty + 32 * i];
                    unsigned long long ap0 = packf2(a2.x, a2.x);
                    unsigned long long ap1 = packf2(a2.y, a2.y);
                    #pragma unroll
                    for (int j = 0; j < 4; j++) {
                        fmaf2(accp[2 * i + 0][j], ap0, bp[j]);
                        fmaf2(accp[2 * i + 1][j], ap1, bp[j]);
                    }
                }
            }
        }

        #pragma unroll
        for (int j = 0; j < 4; j++) {
            int c0 = ct + 2 * tx + 32 * j;
            #pragma unroll
            for (int r = 0; r < 8; r++) {
                float v0, v1;
                unpackf2(accp[r][j], v0, v1);
                if (v0 > best[r]) { best[r] = v0; bidx[r] = c0; }
                if (v1 > best[r]) { best[r] = v1; bidx[r] = c0 + 1; }
            }
        }
    }

    #pragma unroll
    for (int off = 8; off; off >>= 1) {
        #pragma unroll
        for (int r = 0; r < 8; r++) {
            float ov = __shfl_xor_sync(0xffffffffu, best[r], off);
            int   oi = __shfl_xor_sync(0xffffffffu, bidx[r], off);
            if (ov > best[r] || (ov == best[r] && oi < bidx[r])) {
                best[r] = ov; bidx[r] = oi;
            }
        }
    }
    if (tx == 0) {
        #pragma unroll
        for (int r = 0; r < 8; r++) {
            int slot = base + 2 * ty + 32 * (r >> 1) + (r & 1);
            int grow = (slot < count) ? g_flag_rows[slot] : g_flag_rows[0];
            g_ids[grow] = bidx[r];
        }
    }
}

// ---------------------------------------------------------------------------
// residual update: res -= cb[id], hard += cb[id], emit id; reset flag counter
// ---------------------------------------------------------------------------
__global__ __launch_bounds__(256) void update_kernel(const float* __restrict__ cb,
                                                     float* __restrict__ hard,
                                                     float* __restrict__ out_ids,
                                                     int q) {
    int t = blockIdx.x * 256 + threadIdx.x;
    if (t == 0) g_flag_count = 0;
    int row = t >> 7;
    int c   = (t & 127) << 2;
    int id  = g_ids[row];
    float4 cv = *(const float4*)(cb + (size_t)id * DIM + c);
    size_t off = (size_t)row * DIM + c;
    float4 r = *(float4*)(g_res + off);
    r.x -= cv.x; r.y -= cv.y; r.z -= cv.z; r.w -= cv.w;
    *(float4*)(g_res + off) = r;
    float4 h = *(float4*)(hard + off);
    h.x += cv.x; h.y += cv.y; h.z += cv.z; h.w += cv.w;
    *(float4*)(hard + off) = h;
    if (out_ids != nullptr && (t & 127) == 0)
        out_ids[(size_t)row * NQ + q] = (float)id;
}

// ---------------------------------------------------------------------------
extern "C" void kernel_launch(void* const* d_in, const int* in_sizes, int n_in,
                              void* d_out, int out_size) {
    const float* x  = (const float*)d_in[0];   // [N, D] fp32
    const float* cb = (const float*)d_in[1];   // [Q, K, D] fp32
    float* out      = (float*)d_out;

    cudaFuncSetAttribute(fast_gemm_kernel,
                         cudaFuncAttributeMaxDynamicSharedMemorySize, SMEM_BYTES);

    const size_t nd = (size_t)N_ROWS * DIM;
    float* out_ids  = ((size_t)out_size >= nd + (size_t)N_ROWS * NQ)
                      ? out + nd : nullptr;

    init_kernel<<<N_ROWS * DIM / 1024, 256>>>(x, out);

    for (int q = 0; q < NQ; q++) {
        const float* cbq = cb + (size_t)q * NK * DIM;
        cb_norm_kernel<<<NK / 256, 256>>>(cbq);
        cb_div_split_kernel<<<NK * DIM / 8 / 256, 256>>>(cbq);
        res_norm_kernel<<<N_ROWS / 256, 256>>>();
        res_div_split_kernel<<<N_ROWS * DIM / 8 / 256, 256>>>();
        fast_gemm_kernel<<<N_ROWS / 64, 256, SMEM_BYTES>>>();
        rescore_kernel<<<N_ROWS / 128, 256>>>();
        update_kernel<<<N_ROWS * 128 / 256, 256>>>(cbq, out, out_ids, q);
    }
}

// round 10
// speedup vs baseline: 5.0596x; 5.0596x over previous
#include <cuda_runtime.h>
#include <cuda_bf16.h>
#include <cstdint>
#include <math.h>

#define N_ROWS 32768
#define DIM    512
#define NQ     8
#define NK     4096
#define THRESH 6e-4f

// fast kernel geometry
#define BM 128
#define BN 128
#define BK 64
#define CTILES (NK / BN)   // 32
#define KCH    (DIM / BK)  // 8

// dynamic smem layout (bytes)
#define SA_OFF   0                     // A: 2 stages x 16KB
#define SB_OFF   32768                 // B: 2 stages x 16KB
#define RED_OFF  65536                 // 4*512 f + 4*512 f + 4*512 i = 6KB... (512 ea)
#define SMEM_FAST (65536 + 512 * 4 * 3)

// Scratch (__device__ globals, referenced by name in kernels only)
__device__ float g_res[(size_t)N_ROWS * DIM];
__device__ float g_anorm[(size_t)N_ROWS * DIM];
__device__ float g_bnorm[(size_t)NK * DIM];
__device__ float g_rnorm[N_ROWS];
__device__ float g_cnorm[NK];
__device__ int   g_ids[N_ROWS];
__device__ int   g_flag_count;
__device__ int   g_flag_rows[N_ROWS];
__device__ uint4 g_ahi[(size_t)N_ROWS * DIM / 8];   // bf16 [N_ROWS][512]
__device__ uint4 g_bhi[(size_t)NK * DIM / 8];       // bf16 [NK][512]
__device__ float g_pbest[(size_t)N_ROWS * 8];
__device__ int   g_pidx[(size_t)N_ROWS * 8];

// ---------------------------------------------------------------------------
// helpers
// ---------------------------------------------------------------------------
__device__ __forceinline__ uint32_t smem_u32(const void* p) {
    uint32_t a;
    asm("{ .reg .u64 t; cvta.to.shared.u64 t, %1; cvt.u32.u64 %0, t; }"
        : "=r"(a) : "l"(p));
    return a;
}
__device__ __forceinline__ unsigned long long packf2(float lo, float hi) {
    unsigned long long r;
    asm("mov.b64 %0, {%1, %2};" : "=l"(r) : "f"(lo), "f"(hi));
    return r;
}
__device__ __forceinline__ void fmaf2(unsigned long long& d,
                                      unsigned long long a, unsigned long long b) {
    asm("fma.rn.f32x2 %0, %1, %2, %0;" : "+l"(d) : "l"(a), "l"(b));
}
__device__ __forceinline__ void unpackf2(unsigned long long p, float& lo, float& hi) {
    asm("mov.b64 {%0, %1}, %2;" : "=f"(lo), "=f"(hi) : "l"(p));
}
__device__ __forceinline__ unsigned bf2u(float x, float y) {
    __nv_bfloat162 v = __floats2bfloat162_rn(x, y);
    return *(unsigned*)&v;
}
__device__ __forceinline__ void cp16(uint32_t dst, const void* src) {
    asm volatile("cp.async.cg.shared.global [%0], [%1], 16;"
                 :: "r"(dst), "l"(src));
}
#define CP_COMMIT() asm volatile("cp.async.commit_group;" ::: "memory")
#define CP_WAIT(n)  asm volatile("cp.async.wait_group %0;" :: "n"(n) : "memory")
__device__ __forceinline__ void ldsm4(unsigned r[4], uint32_t addr) {
    asm volatile("ldmatrix.sync.aligned.m8n8.x4.shared.b16 {%0,%1,%2,%3}, [%4];"
                 : "=r"(r[0]), "=r"(r[1]), "=r"(r[2]), "=r"(r[3]) : "r"(addr));
}
__device__ __forceinline__ void mma16816(float c[4], const unsigned a[4],
                                         unsigned b0, unsigned b1) {
    asm volatile(
        "mma.sync.aligned.m16n8k16.row.col.f32.bf16.bf16.f32 "
        "{%0,%1,%2,%3}, {%4,%5,%6,%7}, {%8,%9}, {%0,%1,%2,%3};"
        : "+f"(c[0]), "+f"(c[1]), "+f"(c[2]), "+f"(c[3])
        : "r"(a[0]), "r"(a[1]), "r"(a[2]), "r"(a[3]), "r"(b0), "r"(b1));
}
#define SWZ128(bo) ((bo) ^ (((bo) >> 3) & 0x70))

// ---------------------------------------------------------------------------
// init / norms / split (proven bit-exact recipe)
// ---------------------------------------------------------------------------
__global__ __launch_bounds__(256) void init_kernel(const float* __restrict__ x,
                                                   float* __restrict__ hard) {
    if (blockIdx.x == 0 && threadIdx.x == 0) g_flag_count = 0;
    size_t i = ((size_t)blockIdx.x * 256 + threadIdx.x) * 4;
    float4 v = *(const float4*)(x + i);
    *(float4*)(g_res + i) = v;
    *(float4*)(hard + i) = make_float4(0.f, 0.f, 0.f, 0.f);
}

__device__ __forceinline__ float seq_row_norm(const float* __restrict__ s) {
    float acc = 0.f;
    #pragma unroll 8
    for (int i = 0; i < DIM; i += 4) {
        float4 v = *(const float4*)(s + i);
        acc = __fadd_rn(acc, __fmul_rn(v.x, v.x));
        acc = __fadd_rn(acc, __fmul_rn(v.y, v.y));
        acc = __fadd_rn(acc, __fmul_rn(v.z, v.z));
        acc = __fadd_rn(acc, __fmul_rn(v.w, v.w));
    }
    return fmaxf(__fsqrt_rn(acc), 1e-12f);
}
__global__ __launch_bounds__(256) void res_norm_kernel() {
    int r = blockIdx.x * 256 + threadIdx.x;
    g_rnorm[r] = seq_row_norm(g_res + (size_t)r * DIM);
}
__global__ __launch_bounds__(256) void cb_norm_kernel(const float* __restrict__ cbq) {
    int r = blockIdx.x * 256 + threadIdx.x;
    g_cnorm[r] = seq_row_norm(cbq + (size_t)r * DIM);
}

__device__ __forceinline__ void div_split8(const float* __restrict__ src, float n,
                                           float* __restrict__ anorm,
                                           uint4* __restrict__ hi4) {
    float an[8];
    float4 v0 = *(const float4*)(src);
    float4 v1 = *(const float4*)(src + 4);
    an[0] = __fdiv_rn(v0.x, n); an[1] = __fdiv_rn(v0.y, n);
    an[2] = __fdiv_rn(v0.z, n); an[3] = __fdiv_rn(v0.w, n);
    an[4] = __fdiv_rn(v1.x, n); an[5] = __fdiv_rn(v1.y, n);
    an[6] = __fdiv_rn(v1.z, n); an[7] = __fdiv_rn(v1.w, n);
    *(float4*)(anorm)     = make_float4(an[0], an[1], an[2], an[3]);
    *(float4*)(anorm + 4) = make_float4(an[4], an[5], an[6], an[7]);
    uint4 uh;
    uh.x = bf2u(an[0], an[1]); uh.y = bf2u(an[2], an[3]);
    uh.z = bf2u(an[4], an[5]); uh.w = bf2u(an[6], an[7]);
    *hi4 = uh;
}
__global__ __launch_bounds__(256) void res_div_split_kernel() {
    size_t g = (size_t)blockIdx.x * 256 + threadIdx.x;
    size_t i = g * 8;
    div_split8(g_res + i, g_rnorm[i >> 9], g_anorm + i, &g_ahi[g]);
}
__global__ __launch_bounds__(256) void cb_div_split_kernel(const float* __restrict__ cbq) {
    size_t g = (size_t)blockIdx.x * 256 + threadIdx.x;
    size_t i = g * 8;
    div_split8(cbq + i, g_cnorm[i >> 9], g_bnorm + i, &g_bhi[g]);
}

// ---------------------------------------------------------------------------
// FAST PASS: bf16 mma.sync GEMM (hi-term only) + top-2 + flagging.
// 256 thr / 8 warps (2m x 4n), tiles 128x128x64, cp.async double buffer,
// ldmatrix fragments from SW128-swizzled smem.
// ---------------------------------------------------------------------------
__global__ __launch_bounds__(256, 2) void fast_gemm_kernel() {
    extern __shared__ char smem[];
    const uint32_t sb = smem_u32(smem);
    float* rbest = (float*)(smem + RED_OFF);
    float* rsec  = rbest + 512;
    int*   ridx  = (int*)(rsec + 512);

    const int tid  = threadIdx.x;
    const int lane = tid & 31, wid = tid >> 5;
    const int wm = wid >> 2, wn = wid & 3;
    const int g4 = lane >> 2, tig = lane & 3;
    const int row0 = blockIdx.x * BM;

    const __nv_bfloat16* Ahi = (const __nv_bfloat16*)g_ahi;
    const __nv_bfloat16* Bhi = (const __nv_bfloat16*)g_bhi;

    // ldmatrix per-lane source coordinates (row within tile, 16B chunk parity)
    const int lrow = lane & 15;
    const int lchk = lane >> 4;

    float best[8], sec[8];
    int   bidx[8];
    #pragma unroll
    for (int i = 0; i < 8; i++) { best[i] = -3.4e38f; sec[i] = -3.4e38f; bidx[i] = 0; }

    for (int ct = 0; ct < CTILES; ct++) {
        float acc[4][4][4];
        #pragma unroll
        for (int mf = 0; mf < 4; mf++)
            #pragma unroll
            for (int nf = 0; nf < 4; nf++)
                #pragma unroll
                for (int c = 0; c < 4; c++) acc[mf][nf][c] = 0.f;

        // prefetch chunk 0 into stage 0
        {
            #pragma unroll
            for (int i = 0; i < 4; i++) {
                int idx = tid + i * 256;               // 0..1023
                int r = idx >> 3, c16 = idx & 7;
                cp16(sb + SA_OFF + SWZ128(r * 128 + c16 * 16),
                     Ahi + (size_t)(row0 + r) * DIM + c16 * 8);
                cp16(sb + SB_OFF + SWZ128(r * 128 + c16 * 16),
                     Bhi + (size_t)(ct * BN + r) * DIM + c16 * 8);
            }
            CP_COMMIT();
        }

        for (int kc = 0; kc < KCH; kc++) {
            if (kc + 1 < KCH) {
                int st = (kc + 1) & 1;
                int kk = (kc + 1) * BK;
                #pragma unroll
                for (int i = 0; i < 4; i++) {
                    int idx = tid + i * 256;
                    int r = idx >> 3, c16 = idx & 7;
                    cp16(sb + SA_OFF + st * 16384 + SWZ128(r * 128 + c16 * 16),
                         Ahi + (size_t)(row0 + r) * DIM + kk + c16 * 8);
                    cp16(sb + SB_OFF + st * 16384 + SWZ128(r * 128 + c16 * 16),
                         Bhi + (size_t)(ct * BN + r) * DIM + kk + c16 * 8);
                }
                CP_COMMIT();
                CP_WAIT(1);
            } else {
                CP_WAIT(0);
            }
            __syncthreads();

            const uint32_t ab = sb + SA_OFF + (kc & 1) * 16384;
            const uint32_t bb = sb + SB_OFF + (kc & 1) * 16384;

            #pragma unroll
            for (int ks = 0; ks < 4; ks++) {
                const int chk = ks * 2 + lchk;
                unsigned a[4][4];
                #pragma unroll
                for (int mf = 0; mf < 4; mf++) {
                    int r = wm * 64 + mf * 16 + lrow;
                    ldsm4(a[mf], ab + SWZ128(r * 128 + chk * 16));
                }
                unsigned b[2][4];
                #pragma unroll
                for (int nf2 = 0; nf2 < 2; nf2++) {
                    int r = wn * 32 + nf2 * 16 + lrow;
                    ldsm4(b[nf2], bb + SWZ128(r * 128 + chk * 16));
                }
                #pragma unroll
                for (int mf = 0; mf < 4; mf++) {
                    #pragma unroll
                    for (int nf = 0; nf < 4; nf++) {
                        const int n2 = nf >> 1, h = nf & 1;
                        mma16816(acc[mf][nf], a[mf], b[n2][h], b[n2][h + 2]);
                    }
                }
            }
            __syncthreads();
        }

        // epilogue: per-thread top-2, columns ascending (nf asc, then +0,+1)
        #pragma unroll
        for (int nf = 0; nf < 4; nf++) {
            int colb = ct * BN + wn * 32 + nf * 8 + tig * 2;
            #pragma unroll
            for (int mf = 0; mf < 4; mf++) {
                #pragma unroll
                for (int h = 0; h < 2; h++) {
                    int slot = mf * 2 + h;
                    float v0 = acc[mf][nf][h * 2 + 0];
                    float v1 = acc[mf][nf][h * 2 + 1];
                    if (v0 > best[slot]) { sec[slot] = best[slot]; best[slot] = v0; bidx[slot] = colb; }
                    else if (v0 > sec[slot]) sec[slot] = v0;
                    if (v1 > best[slot]) { sec[slot] = best[slot]; best[slot] = v1; bidx[slot] = colb + 1; }
                    else if (v1 > sec[slot]) sec[slot] = v1;
                }
            }
        }
    }

    // reduce over the 4 tig-lanes sharing each row
    #pragma unroll
    for (int off = 1; off <= 2; off <<= 1) {
        #pragma unroll
        for (int sl = 0; sl < 8; sl++) {
            float ob = __shfl_xor_sync(0xffffffffu, best[sl], off);
            float os = __shfl_xor_sync(0xffffffffu, sec[sl], off);
            int   oi = __shfl_xor_sync(0xffffffffu, bidx[sl], off);
            if (ob > best[sl] || (ob == best[sl] && oi < bidx[sl])) {
                sec[sl] = fmaxf(best[sl], os);
                best[sl] = ob; bidx[sl] = oi;
            } else {
                sec[sl] = fmaxf(sec[sl], ob);
            }
        }
    }

    // cross-warp (wn) merge via smem
    __syncthreads();
    if (tig == 0) {
        #pragma unroll
        for (int sl = 0; sl < 8; sl++) {
            int rowl = wm * 64 + (sl >> 1) * 16 + (sl & 1) * 8 + g4;
            rbest[wn * 128 + rowl] = best[sl];
            rsec [wn * 128 + rowl] = sec[sl];
            ridx [wn * 128 + rowl] = bidx[sl];
        }
    }
    __syncthreads();
    if (tid < 128) {
        float b = -3.4e38f, s2 = -3.4e38f; int bi = 0;
        #pragma unroll
        for (int w = 0; w < 4; w++) {
            float wb = rbest[w * 128 + tid], ws = rsec[w * 128 + tid];
            int   wi = ridx[w * 128 + tid];
            if (wb > b || (wb == b && wi < bi)) {
                s2 = fmaxf(b, ws); b = wb; bi = wi;
            } else {
                s2 = fmaxf(s2, wb);
            }
        }
        int row = row0 + tid;
        g_ids[row] = bi;
        if (b - s2 < THRESH) {
            int slot = atomicAdd(&g_flag_count, 1);
            g_flag_rows[slot] = row;
        }
    }
}

// ---------------------------------------------------------------------------
// EXACT RESCORE (bit-exact FFMA2), 8-way column-sliced (proven)
// ---------------------------------------------------------------------------
__global__ __launch_bounds__(256) void rescore_kernel() {
    const int count = g_flag_count;
    const int base  = blockIdx.x * 128;
    if (base >= count) return;
    const int slice = blockIdx.y;
    const int cs0   = slice * 512;

    __shared__ float As[32][130];
    __shared__ float Bs[32][130];

    const int tid = threadIdx.x;
    const int tx  = tid & 15;
    const int ty  = tid >> 4;

    float best[8];
    int   bidx[8];
    #pragma unroll
    for (int r = 0; r < 8; r++) { best[r] = -3.4e38f; bidx[r] = 0; }

    for (int ct = cs0; ct < cs0 + 512; ct += 128) {
        unsigned long long accp[8][4];
        #pragma unroll
        for (int r = 0; r < 8; r++)
            #pragma unroll
            for (int j = 0; j < 4; j++) accp[r][j] = 0ull;

        for (int kk = 0; kk < DIM; kk += 32) {
            __syncthreads();
            #pragma unroll
            for (int t = 0; t < 4; t++) {
                int f = tid + t * 256;
                int r = f >> 3;
                int c = (f & 7) << 2;
                int slot = base + r;
                int grow = (slot < count) ? g_flag_rows[slot] : g_flag_rows[0];
                float4 va = *(const float4*)(g_anorm + (size_t)grow * DIM + kk + c);
                As[c + 0][r] = va.x; As[c + 1][r] = va.y;
                As[c + 2][r] = va.z; As[c + 3][r] = va.w;
                float4 vb = *(const float4*)(g_bnorm + (size_t)(ct + r) * DIM + kk + c);
                Bs[c + 0][r] = vb.x; Bs[c + 1][r] = vb.y;
                Bs[c + 2][r] = vb.z; Bs[c + 3][r] = vb.w;
            }
            __syncthreads();

            #pragma unroll
            for (int k = 0; k < 32; k++) {
                unsigned long long bp[4];
                #pragma unroll
                for (int j = 0; j < 4; j++) {
                    float2 b2 = *(const float2*)&Bs[k][2 * tx + 32 * j];
                    bp[j] = packf2(b2.x, b2.y);
                }
                #pragma unroll
                for (int i = 0; i < 4; i++) {
                    float2 a2 = *(const float2*)&As[k][2 * ty + 32 * i];
                    unsigned long long ap0 = packf2(a2.x, a2.x);
                    unsigned long long ap1 = packf2(a2.y, a2.y);
                    #pragma unroll
                    for (int j = 0; j < 4; j++) {
                        fmaf2(accp[2 * i + 0][j], ap0, bp[j]);
                        fmaf2(accp[2 * i + 1][j], ap1, bp[j]);
                    }
                }
            }
        }

        #pragma unroll
        for (int j = 0; j < 4; j++) {
            int c0 = ct + 2 * tx + 32 * j;
            #pragma unroll
            for (int r = 0; r < 8; r++) {
                float v0, v1;
                unpackf2(accp[r][j], v0, v1);
                if (v0 > best[r]) { best[r] = v0; bidx[r] = c0; }
                if (v1 > best[r]) { best[r] = v1; bidx[r] = c0 + 1; }
            }
        }
    }

    #pragma unroll
    for (int off = 8; off; off >>= 1) {
        #pragma unroll
        for (int r = 0; r < 8; r++) {
            float ov = __shfl_xor_sync(0xffffffffu, best[r], off);
            int   oi = __shfl_xor_sync(0xffffffffu, bidx[r], off);
            if (ov > best[r] || (ov == best[r] && oi < bidx[r])) {
                best[r] = ov; bidx[r] = oi;
            }
        }
    }
    if (tx == 0) {
        #pragma unroll
        for (int r = 0; r < 8; r++) {
            int slot = base + 2 * ty + 32 * (r >> 1) + (r & 1);
            if (slot < count) {
                g_pbest[(size_t)slot * 8 + slice] = best[r];
                g_pidx[(size_t)slot * 8 + slice]  = bidx[r];
            }
        }
    }
}

__global__ __launch_bounds__(128) void merge_kernel() {
    int t = blockIdx.x * 128 + threadIdx.x;
    if (t >= g_flag_count) return;
    float b = -3.4e38f; int bi = 0;
    #pragma unroll
    for (int j = 0; j < 8; j++) {
        float pb = g_pbest[(size_t)t * 8 + j];
        if (pb > b) { b = pb; bi = g_pidx[(size_t)t * 8 + j]; }
    }
    g_ids[g_flag_rows[t]] = bi;
}

// ---------------------------------------------------------------------------
// residual update; resets flag counter for next stage / next replay
// ---------------------------------------------------------------------------
__global__ __launch_bounds__(256) void update_kernel(const float* __restrict__ cb,
                                                     float* __restrict__ hard,
                                                     float* __restrict__ out_ids,
                                                     int q) {
    int t = blockIdx.x * 256 + threadIdx.x;
    if (t == 0) g_flag_count = 0;
    int row = t >> 7;
    int c   = (t & 127) << 2;
    int id  = g_ids[row];
    float4 cv = *(const float4*)(cb + (size_t)id * DIM + c);
    size_t off = (size_t)row * DIM + c;
    float4 r = *(float4*)(g_res + off);
    r.x -= cv.x; r.y -= cv.y; r.z -= cv.z; r.w -= cv.w;
    *(float4*)(g_res + off) = r;
    float4 h = *(float4*)(hard + off);
    h.x += cv.x; h.y += cv.y; h.z += cv.z; h.w += cv.w;
    *(float4*)(hard + off) = h;
    if (out_ids != nullptr && (t & 127) == 0)
        out_ids[(size_t)row * NQ + q] = (float)id;
}

// ---------------------------------------------------------------------------
extern "C" void kernel_launch(void* const* d_in, const int* in_sizes, int n_in,
                              void* d_out, int out_size) {
    const float* x  = (const float*)d_in[0];
    const float* cb = (const float*)d_in[1];
    float* out      = (float*)d_out;

    cudaFuncSetAttribute(fast_gemm_kernel,
                         cudaFuncAttributeMaxDynamicSharedMemorySize, SMEM_FAST);

    const size_t nd = (size_t)N_ROWS * DIM;
    float* out_ids  = ((size_t)out_size >= nd + (size_t)N_ROWS * NQ)
                      ? out + nd : nullptr;

    init_kernel<<<N_ROWS * DIM / 1024, 256>>>(x, out);

    for (int q = 0; q < NQ; q++) {
        const float* cbq = cb + (size_t)q * NK * DIM;
        cb_norm_kernel<<<NK / 256, 256>>>(cbq);
        cb_div_split_kernel<<<NK * DIM / 8 / 256, 256>>>(cbq);
        res_norm_kernel<<<N_ROWS / 256, 256>>>();
        res_div_split_kernel<<<N_ROWS * DIM / 8 / 256, 256>>>();
        fast_gemm_kernel<<<N_ROWS / BM, 256, SMEM_FAST>>>();
        rescore_kernel<<<dim3(N_ROWS / 128, 8), 256>>>();
        merge_kernel<<<N_ROWS / 128, 128>>>();
        update_kernel<<<N_ROWS * 128 / 256, 256>>>(cbq, out, out_ids, q);
    }
}